// round 4
// baseline (speedup 1.0000x reference)
#include <cuda_runtime.h>
#include <cstdint>
#include <cfloat>

#define D_EMBED 512
#define T_TOK   16384      // number of input tokens (4*4096)
#define N_CODE  8192       // codebook entries
#define DECAYF  0.99f
#define EPSF    1e-8f

// NO __device__ globals: all scratch lives in the out_kw region of d_out
// (it is the last output to be written; scratch there is dead by then).

// ---------------- key norms: ||k||^2 per codebook row ----------------------
__global__ void k_knorm(const float* __restrict__ kw, float* __restrict__ knorm) {
    int warp = threadIdx.x >> 5, lane = threadIdx.x & 31;
    int row  = blockIdx.x * 8 + warp;
    const float4* p = (const float4*)(kw + (size_t)row * D_EMBED);
    float s = 0.f;
    #pragma unroll
    for (int q = 0; q < 4; q++) {
        float4 v = p[q * 32 + lane];
        s += v.x * v.x + v.y * v.y + v.z * v.z + v.w * v.w;
    }
    #pragma unroll
    for (int o = 16; o; o >>= 1) s += __shfl_xor_sync(0xffffffffu, s, o);
    if (!lane) knorm[row] = s;
}

// ---------------- packed fp32 helpers ---------------------------------------
__device__ __forceinline__ unsigned long long dup2(float x) {
    unsigned long long r;
    unsigned int u = __float_as_uint(x);
    asm("mov.b64 %0, {%1, %1};" : "=l"(r) : "r"(u));
    return r;
}
__device__ __forceinline__ void fma2(unsigned long long& acc,
                                     unsigned long long a, unsigned long long b) {
    asm("fma.rn.f32x2 %0, %1, %2, %0;" : "+l"(acc) : "l"(a), "l"(b));
}
__device__ __forceinline__ float2 unpack2(unsigned long long v) {
    unsigned int lo, hi;
    asm("mov.b64 {%0, %1}, %2;" : "=r"(lo), "=r"(hi) : "l"(v));
    return make_float2(__uint_as_float(lo), __uint_as_float(hi));
}

// ---------------- fused GEMM + argmin ---------------------------------------
// Block: 64 tokens x (all 8192 codes, 64 at a time). 256 threads, 4x4 microtile
// via f32x2 (2 m-lanes packed). Reads x / key_w ROW-MAJOR; transposes per-tile
// into smem ([k][m], [k][n] dup-pairs, stride 68 -> aligned LDS.128 reads).
// score = ||k||^2 - 2 x.k ; running argmin with first-index tiebreak.
#define TS 68   // smem k-row stride (floats / ull entries)
__global__ __launch_bounds__(256) void k_gemm_argmin(
        const float* __restrict__ x, const float* __restrict__ kwm,
        const float* __restrict__ knorm, int* __restrict__ out_idx) {
    __shared__ __align__(16) float              As[32 * TS];   // [dd][m]
    __shared__ __align__(16) unsigned long long Bs[32 * TS];   // [dd][n] dup pairs
    __shared__ float redv[64 * 16];
    __shared__ int   redi[64 * 16];

    const int tid = threadIdx.x;
    const int tx = tid & 15, ty = tid >> 4;     // tx -> m group, ty -> n group
    const int m_base = blockIdx.x * 64;

    float best[4]; int bidx[4];
    #pragma unroll
    for (int r = 0; r < 4; r++) { best[r] = FLT_MAX; bidx[r] = 0; }

    for (int nt = 0; nt < N_CODE / 64; nt++) {
        const int n_base = nt * 64;
        unsigned long long acc[2][4];
        #pragma unroll
        for (int p = 0; p < 2; p++)
            #pragma unroll
            for (int j = 0; j < 4; j++) acc[p][j] = 0ull;

        for (int dk0 = 0; dk0 < D_EMBED; dk0 += 32) {
            __syncthreads();
            // fill A chunk: 64 rows x 32 k (512 float4 reads, 2 per thread),
            // transposed into As[k][m]
            {
                int i = tid;
                #pragma unroll
                for (int itr = 0; itr < 2; itr++, i += 256) {
                    int row = i >> 3, c = i & 7;            // row: m, c: float4 within 32 k
                    float4 v = *(const float4*)(x + (size_t)(m_base + row) * D_EMBED
                                                  + dk0 + c * 4);
                    As[(c * 4 + 0) * TS + row] = v.x;
                    As[(c * 4 + 1) * TS + row] = v.y;
                    As[(c * 4 + 2) * TS + row] = v.z;
                    As[(c * 4 + 3) * TS + row] = v.w;
                }
            }
            // fill B chunk: 64 rows x 32 k, transposed + duplicated into Bs[k][n]
            {
                int i = tid;
                #pragma unroll
                for (int itr = 0; itr < 2; itr++, i += 256) {
                    int row = i >> 3, c = i & 7;
                    float4 v = *(const float4*)(kwm + (size_t)(n_base + row) * D_EMBED
                                                    + dk0 + c * 4);
                    Bs[(c * 4 + 0) * TS + row] = dup2(v.x);
                    Bs[(c * 4 + 1) * TS + row] = dup2(v.y);
                    Bs[(c * 4 + 2) * TS + row] = dup2(v.z);
                    Bs[(c * 4 + 3) * TS + row] = dup2(v.w);
                }
            }
            __syncthreads();

            #pragma unroll
            for (int dd = 0; dd < 32; dd++) {
                // a: (m0,m1),(m2,m3) packed as two f32x2 (contiguous floats)
                ulonglong2 av = *(const ulonglong2*)&As[dd * TS + tx * 4];
                const ulonglong2* bb = (const ulonglong2*)(Bs + dd * TS + ty * 4);
                ulonglong2 b01 = bb[0], b23 = bb[1];
                fma2(acc[0][0], av.x, b01.x); fma2(acc[1][0], av.y, b01.x);
                fma2(acc[0][1], av.x, b01.y); fma2(acc[1][1], av.y, b01.y);
                fma2(acc[0][2], av.x, b23.x); fma2(acc[1][2], av.y, b23.x);
                fma2(acc[0][3], av.x, b23.y); fma2(acc[1][3], av.y, b23.y);
            }
        }
        // epilogue: scores + running argmin (n ascending => first-index tiebreak)
        #pragma unroll
        for (int j = 0; j < 4; j++) {
            int n = n_base + ty * 4 + j;
            float kn = knorm[n];
            #pragma unroll
            for (int p = 0; p < 2; p++) {
                float2 d2 = unpack2(acc[p][j]);
                int r0 = 2 * p, r1 = 2 * p + 1;
                float s0 = kn - 2.f * d2.x;
                float s1 = kn - 2.f * d2.y;
                if (s0 < best[r0] || (s0 == best[r0] && n < bidx[r0])) { best[r0] = s0; bidx[r0] = n; }
                if (s1 < best[r1] || (s1 == best[r1] && n < bidx[r1])) { best[r1] = s1; bidx[r1] = n; }
            }
        }
    }

    // cross-thread (ty) reduction per token row
    __syncthreads();
    #pragma unroll
    for (int r = 0; r < 4; r++) {
        redv[(tx * 4 + r) * 16 + ty] = best[r];
        redi[(tx * 4 + r) * 16 + ty] = bidx[r];
    }
    __syncthreads();
    if (tid < 64) {
        float bv = redv[tid * 16]; int bi = redi[tid * 16];
        #pragma unroll
        for (int j = 1; j < 16; j++) {
            float v = redv[tid * 16 + j]; int ii = redi[tid * 16 + j];
            if (v < bv || (v == bv && ii < bi)) { bv = v; bi = ii; }
        }
        out_idx[m_base + tid] = bi;
    }
}

// ---------------- elementwise decay copy (grid-stride) ----------------------
__global__ void k_scale(const float* __restrict__ src, float* __restrict__ dst, int n4) {
    for (int i = blockIdx.x * blockDim.x + threadIdx.x; i < n4;
         i += gridDim.x * blockDim.x) {
        float4 v = ((const float4*)src)[i];
        v.x *= DECAYF; v.y *= DECAYF; v.z *= DECAYF; v.w *= DECAYF;
        ((float4*)dst)[i] = v;
    }
}

// ---------------- quantized output + EMA scatter -----------------------------
__global__ void k_scatter(const float* __restrict__ x, const float* __restrict__ vw,
                          const int* __restrict__ idxs,
                          float* __restrict__ out_q, float* __restrict__ out_ew,
                          float* __restrict__ out_en) {
    const int t = blockIdx.x;
    const int idx = idxs[t];
    const int d4 = threadIdx.x;            // 128 threads * float4 = 512
    float4 xv = ((const float4*)(x  + (size_t)t   * D_EMBED))[d4];
    float4 vv = ((const float4*)(vw + (size_t)idx * D_EMBED))[d4];
    float4 q = make_float4(xv.x + vv.x, xv.y + vv.y, xv.z + vv.z, xv.w + vv.w);
    ((float4*)(out_q + (size_t)t * D_EMBED))[d4] = q;

    const float c = (1.0f - DECAYF) * ((float)N_CODE / (float)T_TOK);  // 0.005
    float* ew = out_ew + (size_t)idx * D_EMBED + d4 * 4;
    atomicAdd(ew + 0, c * xv.x);
    atomicAdd(ew + 1, c * xv.y);
    atomicAdd(ew + 2, c * xv.z);
    atomicAdd(ew + 3, c * xv.w);
    if (d4 == 0) atomicAdd(out_en + idx, c);
}

// ---------------- key_w_new = ema_w_new / sz  (n re-reduced per block) -------
__global__ void k_finalize(const float* __restrict__ en, const float* __restrict__ ew,
                           float* __restrict__ kw) {
    __shared__ float sred[4];
    const int tid = threadIdx.x;           // 128 threads
    // block-local reduction of n = sum(en): en is 32KB, L2-resident
    float v = 0.f;
    #pragma unroll
    for (int q = 0; q < N_CODE / 128; q++) v += en[q * 128 + tid];
    #pragma unroll
    for (int o = 16; o; o >>= 1) v += __shfl_xor_sync(0xffffffffu, v, o);
    if ((tid & 31) == 0) sred[tid >> 5] = v;
    __syncthreads();
    float n = sred[0] + sred[1] + sred[2] + sred[3];

    const int k = blockIdx.x;
    float sz = (en[k] + EPSF) / (n + EPSF * (float)N_CODE) * n;
    float inv = 1.0f / sz;
    float4 w = ((const float4*)(ew + (size_t)k * D_EMBED))[tid];
    w.x *= inv; w.y *= inv; w.z *= inv; w.w *= inv;
    ((float4*)(kw + (size_t)k * D_EMBED))[tid] = w;
}

// ---------------- launch --------------------------------------------------------
extern "C" void kernel_launch(void* const* d_in, const int* in_sizes, int n_in,
                              void* d_out, int out_size) {
    const float* x  = (const float*)d_in[0];   // inputs  [4,4096,512]
    const float* kw = (const float*)d_in[1];   // key_w   [8192,512]
    const float* vw = (const float*)d_in[2];   // value_w [8192,512]
    const float* en = (const float*)d_in[3];   // ema_n   [8192]
    const float* ew = (const float*)d_in[4];   // ema_w   [8192,512]

    float* out    = (float*)d_out;
    float* out_q  = out;                                   // 16384*512
    float* out_en = out_q  + (size_t)T_TOK * D_EMBED;      // 8192
    float* out_ew = out_en + N_CODE;                       // 8192*512
    float* out_kw = out_ew + (size_t)N_CODE * D_EMBED;     // 8192*512

    // scratch carved from the out_kw region (dead until k_finalize):
    float* knorm_s = out_kw;                               // 8192 floats
    int*   idx_s   = (int*)(out_kw + N_CODE);              // 16384 ints

    k_knorm<<<N_CODE / 8, 256>>>(kw, knorm_s);
    k_gemm_argmin<<<T_TOK / 64, 256>>>(x, kw, knorm_s, idx_s);

    k_scale<<<(N_CODE / 4 + 255) / 256, 256>>>(en, out_en, N_CODE / 4);
    k_scale<<<2048, 256>>>(ew, out_ew, N_CODE * D_EMBED / 4);
    k_scatter<<<T_TOK, 128>>>(x, vw, idx_s, out_q, out_ew, out_en);
    k_finalize<<<N_CODE, 128>>>(out_en, out_ew, out_kw);
}

// round 6
// speedup vs baseline: 1.5290x; 1.5290x over previous
#include <cuda_runtime.h>
#include <cstdint>
#include <cfloat>

#define D_EMBED 512
#define T_TOK   16384
#define N_CODE  8192
#define DECAYF  0.99f
#define EPSF    1e-8f

// GEMM tiling
#define BM 64
#define BN 128
#define BK 32
#define BSTRIDE 130   // ull stride per k-row of Bs (pad: ~2-way STS, 16B-aligned LDS)

// smem layout (dynamic): As | Bs(2 bufs) | redv | redi
#define SM_AS_BYTES   (D_EMBED * BM * 4)          // 131072
#define SM_BS_BYTES   (2 * BK * BSTRIDE * 8)      // 66560
#define SM_REDV_BYTES (BM * 16 * 4)               // 4096
#define SM_REDI_BYTES (BM * 16 * 4)               // 4096
#define SM_TOTAL (SM_AS_BYTES + SM_BS_BYTES + SM_REDV_BYTES + SM_REDI_BYTES)

// ---------------- key norms ----------------
__global__ void k_knorm(const float* __restrict__ kw, float* __restrict__ knorm) {
    int warp = threadIdx.x >> 5, lane = threadIdx.x & 31;
    int row  = blockIdx.x * 8 + warp;
    const float4* p = (const float4*)(kw + (size_t)row * D_EMBED);
    float s = 0.f;
    #pragma unroll
    for (int q = 0; q < 4; q++) {
        float4 v = p[q * 32 + lane];
        s += v.x * v.x + v.y * v.y + v.z * v.z + v.w * v.w;
    }
    #pragma unroll
    for (int o = 16; o; o >>= 1) s += __shfl_xor_sync(0xffffffffu, s, o);
    if (!lane) knorm[row] = s;
}

// ---------------- packed fp32 helpers ----------------
__device__ __forceinline__ unsigned long long dup2(float x) {
    unsigned long long r;
    unsigned int u = __float_as_uint(x);
    asm("mov.b64 %0, {%1, %1};" : "=l"(r) : "r"(u));
    return r;
}
__device__ __forceinline__ void fma2(unsigned long long& acc,
                                     unsigned long long a, unsigned long long b) {
    asm("fma.rn.f32x2 %0, %1, %2, %0;" : "+l"(acc) : "l"(a), "l"(b));
}
__device__ __forceinline__ float2 unpack2(unsigned long long v) {
    unsigned int lo, hi;
    asm("mov.b64 {%0, %1}, %2;" : "=r"(lo), "=r"(hi) : "l"(v));
    return make_float2(__uint_as_float(lo), __uint_as_float(hi));
}

// ---------------- fused GEMM + argmin ----------------
// Block = 64 tokens. A slab (64x512) resident in smem. B streamed in
// double-buffered 32k x 128n chunks (dup f32x2 pairs). Microtile 4m x 8n
// per thread via f32x2. score = ||k||^2 - 2 x.k; running argmin.
__global__ __launch_bounds__(256) void k_gemm_argmin(
        const float* __restrict__ x, const float* __restrict__ kwm,
        const float* __restrict__ knorm, int* __restrict__ out_idx) {
    extern __shared__ __align__(16) char smem[];
    float*              As   = (float*)smem;                              // [512][64]
    unsigned long long* Bs   = (unsigned long long*)(smem + SM_AS_BYTES); // [2][32][BSTRIDE]
    float*              redv = (float*)(smem + SM_AS_BYTES + SM_BS_BYTES);
    int*                redi = (int*)(smem + SM_AS_BYTES + SM_BS_BYTES + SM_REDV_BYTES);

    const int tid = threadIdx.x;
    const int tx = tid & 15, ty = tid >> 4;     // tx -> 4 m rows, ty -> 8 n cols
    const int m_base = blockIdx.x * BM;

    // ---- load A slab once: As[k][m] ----
    for (int i = tid; i < BM * (D_EMBED / 4); i += 256) {
        int row = i >> 7, c = i & 127;          // row: m, c: float4 along k
        float4 v = *(const float4*)(x + (size_t)(m_base + row) * D_EMBED + c * 4);
        As[(c * 4 + 0) * BM + row] = v.x;
        As[(c * 4 + 1) * BM + row] = v.y;
        As[(c * 4 + 2) * BM + row] = v.z;
        As[(c * 4 + 3) * BM + row] = v.w;
    }
    __syncthreads();

    float best[4]; int bidx[4];
    #pragma unroll
    for (int r = 0; r < 4; r++) { best[r] = FLT_MAX; bidx[r] = 0; }

    for (int nt = 0; nt < N_CODE / BN; nt++) {
        const int n_base = nt * BN;
        unsigned long long acc[2][8];
        #pragma unroll
        for (int p = 0; p < 2; p++)
            #pragma unroll
            for (int j = 0; j < 8; j++) acc[p][j] = 0ull;

        // prefetch chunk 0 and commit to buffer 0
        float4 breg[4];
        #pragma unroll
        for (int t = 0; t < 4; t++) {
            int i = tid + t * 256, row = i >> 3, c = i & 7;
            breg[t] = *(const float4*)(kwm + (size_t)(n_base + row) * D_EMBED + c * 4);
        }
        #pragma unroll
        for (int t = 0; t < 4; t++) {
            int i = tid + t * 256, row = i >> 3, c = i & 7;
            unsigned long long* bp = Bs + (size_t)(c * 4) * BSTRIDE + row;
            bp[0 * BSTRIDE] = dup2(breg[t].x);
            bp[1 * BSTRIDE] = dup2(breg[t].y);
            bp[2 * BSTRIDE] = dup2(breg[t].z);
            bp[3 * BSTRIDE] = dup2(breg[t].w);
        }
        __syncthreads();

        #pragma unroll 2
        for (int ch = 0; ch < D_EMBED / BK; ch++) {
            // prefetch next chunk into regs (latency overlapped with compute)
            if (ch < D_EMBED / BK - 1) {
                int dk = (ch + 1) * BK;
                #pragma unroll
                for (int t = 0; t < 4; t++) {
                    int i = tid + t * 256, row = i >> 3, c = i & 7;
                    breg[t] = *(const float4*)(kwm + (size_t)(n_base + row) * D_EMBED
                                                   + dk + c * 4);
                }
            }
            const unsigned long long* cur = Bs + (ch & 1) * (BK * BSTRIDE);
            const int kbase = ch * BK;
            #pragma unroll
            for (int dd = 0; dd < BK; dd++) {
                ulonglong2 av = *(const ulonglong2*)&As[(kbase + dd) * BM + tx * 4];
                const unsigned long long* bp = cur + (size_t)dd * BSTRIDE + ty * 8;
                ulonglong2 b01 = *(const ulonglong2*)(bp + 0);
                ulonglong2 b23 = *(const ulonglong2*)(bp + 2);
                ulonglong2 b45 = *(const ulonglong2*)(bp + 4);
                ulonglong2 b67 = *(const ulonglong2*)(bp + 6);
                fma2(acc[0][0], av.x, b01.x); fma2(acc[1][0], av.y, b01.x);
                fma2(acc[0][1], av.x, b01.y); fma2(acc[1][1], av.y, b01.y);
                fma2(acc[0][2], av.x, b23.x); fma2(acc[1][2], av.y, b23.x);
                fma2(acc[0][3], av.x, b23.y); fma2(acc[1][3], av.y, b23.y);
                fma2(acc[0][4], av.x, b45.x); fma2(acc[1][4], av.y, b45.x);
                fma2(acc[0][5], av.x, b45.y); fma2(acc[1][5], av.y, b45.y);
                fma2(acc[0][6], av.x, b67.x); fma2(acc[1][6], av.y, b67.x);
                fma2(acc[0][7], av.x, b67.y); fma2(acc[1][7], av.y, b67.y);
            }
            if (ch < D_EMBED / BK - 1) {
                unsigned long long* nxt = Bs + ((ch + 1) & 1) * (BK * BSTRIDE);
                #pragma unroll
                for (int t = 0; t < 4; t++) {
                    int i = tid + t * 256, row = i >> 3, c = i & 7;
                    unsigned long long* bp = nxt + (size_t)(c * 4) * BSTRIDE + row;
                    bp[0 * BSTRIDE] = dup2(breg[t].x);
                    bp[1 * BSTRIDE] = dup2(breg[t].y);
                    bp[2 * BSTRIDE] = dup2(breg[t].z);
                    bp[3 * BSTRIDE] = dup2(breg[t].w);
                }
                __syncthreads();
            }
        }

        // epilogue: scores + running argmin (ascending n => first-index tiebreak)
        #pragma unroll
        for (int j = 0; j < 8; j++) {
            int n = n_base + ty * 8 + j;
            float kn = knorm[n];
            #pragma unroll
            for (int p = 0; p < 2; p++) {
                float2 d2 = unpack2(acc[p][j]);
                int r0 = 2 * p, r1 = 2 * p + 1;
                float s0 = kn - 2.f * d2.x;
                float s1 = kn - 2.f * d2.y;
                if (s0 < best[r0] || (s0 == best[r0] && n < bidx[r0])) { best[r0] = s0; bidx[r0] = n; }
                if (s1 < best[r1] || (s1 == best[r1] && n < bidx[r1])) { best[r1] = s1; bidx[r1] = n; }
            }
        }
        __syncthreads();   // before next nt reuses Bs buffer 0
    }

    // cross-thread (ty) reduction per token row
    #pragma unroll
    for (int r = 0; r < 4; r++) {
        redv[(tx * 4 + r) * 16 + ty] = best[r];
        redi[(tx * 4 + r) * 16 + ty] = bidx[r];
    }
    __syncthreads();
    if (tid < 64) {
        float bv = redv[tid * 16]; int bi = redi[tid * 16];
        #pragma unroll
        for (int j = 1; j < 16; j++) {
            float v = redv[tid * 16 + j]; int ii = redi[tid * 16 + j];
            if (v < bv || (v == bv && ii < bi)) { bv = v; bi = ii; }
        }
        out_idx[m_base + tid] = bi;
    }
}

// ---------------- elementwise decay copy (grid-stride) ----------------
__global__ void k_scale(const float* __restrict__ src, float* __restrict__ dst, int n4) {
    for (int i = blockIdx.x * blockDim.x + threadIdx.x; i < n4;
         i += gridDim.x * blockDim.x) {
        float4 v = ((const float4*)src)[i];
        v.x *= DECAYF; v.y *= DECAYF; v.z *= DECAYF; v.w *= DECAYF;
        ((float4*)dst)[i] = v;
    }
}

// ---------------- quantized output + EMA scatter ----------------
__global__ void k_scatter(const float* __restrict__ x, const float* __restrict__ vw,
                          const int* __restrict__ idxs,
                          float* __restrict__ out_q, float* __restrict__ out_ew,
                          float* __restrict__ out_en) {
    const int t = blockIdx.x;
    const int idx = idxs[t];
    const int d4 = threadIdx.x;            // 128 threads * float4 = 512
    float4 xv = ((const float4*)(x  + (size_t)t   * D_EMBED))[d4];
    float4 vv = ((const float4*)(vw + (size_t)idx * D_EMBED))[d4];
    float4 q = make_float4(xv.x + vv.x, xv.y + vv.y, xv.z + vv.z, xv.w + vv.w);
    ((float4*)(out_q + (size_t)t * D_EMBED))[d4] = q;

    const float c = (1.0f - DECAYF) * ((float)N_CODE / (float)T_TOK);  // 0.005
    float* ew = out_ew + (size_t)idx * D_EMBED + d4 * 4;
    atomicAdd(ew + 0, c * xv.x);
    atomicAdd(ew + 1, c * xv.y);
    atomicAdd(ew + 2, c * xv.z);
    atomicAdd(ew + 3, c * xv.w);
    if (d4 == 0) atomicAdd(out_en + idx, c);
}

// ---------------- key_w_new = ema_w_new / sz (n re-reduced per block) --------
__global__ void k_finalize(const float* __restrict__ en, const float* __restrict__ ew,
                           float* __restrict__ kw) {
    __shared__ float sred[4];
    const int tid = threadIdx.x;           // 128 threads
    float v = 0.f;
    #pragma unroll
    for (int q = 0; q < N_CODE / 128; q++) v += en[q * 128 + tid];
    #pragma unroll
    for (int o = 16; o; o >>= 1) v += __shfl_xor_sync(0xffffffffu, v, o);
    if ((tid & 31) == 0) sred[tid >> 5] = v;
    __syncthreads();
    float n = sred[0] + sred[1] + sred[2] + sred[3];

    const int k = blockIdx.x;
    float sz = (en[k] + EPSF) / (n + EPSF * (float)N_CODE) * n;
    float inv = 1.0f / sz;
    float4 w = ((const float4*)(ew + (size_t)k * D_EMBED))[tid];
    w.x *= inv; w.y *= inv; w.z *= inv; w.w *= inv;
    ((float4*)(kw + (size_t)k * D_EMBED))[tid] = w;
}

// ---------------- launch ----------------
extern "C" void kernel_launch(void* const* d_in, const int* in_sizes, int n_in,
                              void* d_out, int out_size) {
    const float* x  = (const float*)d_in[0];   // inputs  [4,4096,512]
    const float* kw = (const float*)d_in[1];   // key_w   [8192,512]
    const float* vw = (const float*)d_in[2];   // value_w [8192,512]
    const float* en = (const float*)d_in[3];   // ema_n   [8192]
    const float* ew = (const float*)d_in[4];   // ema_w   [8192,512]

    float* out    = (float*)d_out;
    float* out_q  = out;                                   // 16384*512
    float* out_en = out_q  + (size_t)T_TOK * D_EMBED;      // 8192
    float* out_ew = out_en + N_CODE;                       // 8192*512
    float* out_kw = out_ew + (size_t)N_CODE * D_EMBED;     // 8192*512

    // scratch carved from the out_kw region (dead until k_finalize):
    float* knorm_s = out_kw;                               // 8192 floats
    int*   idx_s   = (int*)(out_kw + N_CODE);              // 16384 ints

    cudaFuncSetAttribute(k_gemm_argmin,
                         cudaFuncAttributeMaxDynamicSharedMemorySize, SM_TOTAL);

    k_knorm<<<N_CODE / 8, 256>>>(kw, knorm_s);
    k_gemm_argmin<<<T_TOK / BM, 256, SM_TOTAL>>>(x, kw, knorm_s, idx_s);

    k_scale<<<(N_CODE / 4 + 255) / 256, 256>>>(en, out_en, N_CODE / 4);
    k_scale<<<2048, 256>>>(ew, out_ew, N_CODE * D_EMBED / 4);
    k_scatter<<<T_TOK, 128>>>(x, vw, idx_s, out_q, out_ew, out_en);
    k_finalize<<<N_CODE, 128>>>(out_en, out_ew, out_kw);
}

// round 8
// speedup vs baseline: 6.8495x; 4.4798x over previous
#include <cuda_runtime.h>
#include <cuda_bf16.h>
#include <cstdint>
#include <cfloat>

#define D_EMBED 512
#define T_TOK   16384
#define N_CODE  8192
#define DECAYF  0.99f
#define EPSF    1e-8f

// ---- GEMM tiling ----
#define MBLK    64                 // tokens per block
#define NTILE   128                // codes per n-tile
#define NTILES  (N_CODE / NTILE)   // 64
#define KCH     64                 // bf16 k per chunk (128B rows)
#define NCHUNK  (D_EMBED / KCH)    // 8
#define GTOT    (NTILES * NCHUNK)  // 512
#define A_TILE_B 8192              // 64 rows * 128B
#define B_TILE_B 16384             // 128 rows * 128B
#define STAGE_B  (2 * A_TILE_B + 2 * B_TILE_B)   // 49152
#define SM_STAGE0 4096
#define SM_TOTAL (SM_STAGE0 + 2 * STAGE_B)       // 102400

// ---------------- PTX helpers ----------------
__device__ __forceinline__ uint32_t smem_u32(const void* p) {
    uint32_t a;
    asm("{ .reg .u64 t; cvta.to.shared.u64 t, %1; cvt.u32.u64 %0, t; }" : "=r"(a) : "l"(p));
    return a;
}
#define MBARRIER_INIT(addr, cnt) \
    asm volatile("mbarrier.init.shared.b64 [%0], %1;" :: "r"(addr), "r"(cnt) : "memory")
#define MBARRIER_INVAL(addr) \
    asm volatile("mbarrier.inval.shared.b64 [%0];" :: "r"(addr) : "memory")
#define MBARRIER_EXPECT_TX(addr, tx) \
    asm volatile("mbarrier.arrive.expect_tx.shared.b64 _, [%0], %1;" :: "r"(addr), "r"(tx) : "memory")
#define MBARRIER_WAIT_PARITY(addr, par) do {                                   \
    uint32_t _m = (addr); uint32_t _p = (par); uint32_t _d;                    \
    asm volatile("{\n\t.reg .pred p;\n\t"                                      \
        "mbarrier.try_wait.parity.acquire.cta.shared::cta.b64 p, [%1], %2;\n\t"\
        "selp.b32 %0, 1, 0, p;\n\t}" : "=r"(_d) : "r"(_m), "r"(_p) : "memory");\
    if (!_d) {                                                                 \
        asm volatile("{\n\t.reg .pred P1;\n\t"                                 \
            "W_%=:\n\t"                                                        \
            "mbarrier.try_wait.parity.acquire.cta.shared::cta.b64 P1, [%0], %1, 0x989680;\n\t" \
            "@P1 bra.uni D_%=;\n\tbra.uni W_%=;\n\tD_%=:\n\t}"                 \
            :: "r"(_m), "r"(_p) : "memory");                                   \
    }                                                                          \
} while (0)
__device__ __forceinline__ void bulk_g2s(uint32_t dst, const void* src,
                                         uint32_t bytes, uint32_t mbar) {
    asm volatile("cp.async.bulk.shared::cluster.global.mbarrier::complete_tx::bytes "
                 "[%0], [%1], %2, [%3];"
                 :: "r"(dst), "l"(src), "r"(bytes), "r"(mbar) : "memory");
}
__device__ __forceinline__ void ldsm_x4(uint32_t* r, uint32_t addr) {
    asm volatile("ldmatrix.sync.aligned.m8n8.x4.shared.b16 {%0,%1,%2,%3}, [%4];"
                 : "=r"(r[0]), "=r"(r[1]), "=r"(r[2]), "=r"(r[3]) : "r"(addr));
}
__device__ __forceinline__ void mma_bf16(float* d, const uint32_t* a, const uint32_t* b) {
    asm volatile("mma.sync.aligned.m16n8k16.row.col.f32.bf16.bf16.f32 "
                 "{%0,%1,%2,%3}, {%4,%5,%6,%7}, {%8,%9}, {%0,%1,%2,%3};"
                 : "+f"(d[0]), "+f"(d[1]), "+f"(d[2]), "+f"(d[3])
                 : "r"(a[0]), "r"(a[1]), "r"(a[2]), "r"(a[3]), "r"(b[0]), "r"(b[1]));
}

// ---------------- split fp32 -> bf16 hi/lo in TILED+SWIZZLED global layout ----
// Tile = rows_per_tile x 64 bf16 (128B rows), SW128 XOR swizzle, tiles ordered
// (row_tile * 8 + k_chunk). A 1D bulk copy of one tile reproduces the exact
// smem image ldmatrix expects.
__global__ void k_split_tiled(const float* __restrict__ in, char* __restrict__ hi,
                              char* __restrict__ lo, int total_u4, int rlog2) {
    int idx = blockIdx.x * blockDim.x + threadIdx.x;   // one 16B group (8 bf16)
    if (idx >= total_u4) return;
    int row = idx >> 6, c = idx & 63;                  // 64 groups per 512-k row
    int ch = c >> 3, c16 = c & 7;
    const float4* src = (const float4*)(in + (size_t)row * D_EMBED + c * 8);
    float4 v0 = src[0], v1 = src[1];
    float f[8] = {v0.x, v0.y, v0.z, v0.w, v1.x, v1.y, v1.z, v1.w};
    __nv_bfloat16 h[8], l[8];
    #pragma unroll
    for (int i = 0; i < 8; i++) {
        h[i] = __float2bfloat16(f[i]);
        l[i] = __float2bfloat16(f[i] - __bfloat162float(h[i]));
    }
    int rmask = (1 << rlog2) - 1;
    size_t tbytes = (size_t)128 << rlog2;
    size_t tile = (size_t)(row >> rlog2) * 8 + ch;
    int boff = (row & rmask) * 128 + c16 * 16;
    boff ^= (boff >> 3) & 0x70;
    *(uint4*)(hi + tile * tbytes + boff) = *(uint4*)h;
    *(uint4*)(lo + tile * tbytes + boff) = *(uint4*)l;
}

// ---------------- key norms ----------------
__global__ void k_knorm(const float* __restrict__ kw, float* __restrict__ knorm) {
    int warp = threadIdx.x >> 5, lane = threadIdx.x & 31;
    int row  = blockIdx.x * 8 + warp;
    const float4* p = (const float4*)(kw + (size_t)row * D_EMBED);
    float s = 0.f;
    #pragma unroll
    for (int q = 0; q < 4; q++) {
        float4 v = p[q * 32 + lane];
        s += v.x * v.x + v.y * v.y + v.z * v.z + v.w * v.w;
    }
    #pragma unroll
    for (int o = 16; o; o >>= 1) s += __shfl_xor_sync(0xffffffffu, s, o);
    if (!lane) knorm[row] = s;
}

// ---------------- mma.sync GEMM + argmin ----------------
// 8 warps as 2(m) x 4(n); warp tile 32x32; 3-term bf16 split accumulated into
// one fp32 accum set. score = knorm - 2*x.k; per-thread running argmin.
__global__ __launch_bounds__(256, 2)
void k_gemm_argmin_mma(const char* __restrict__ xhi_t, const char* __restrict__ xlo_t,
                       const char* __restrict__ khi_t, const char* __restrict__ klo_t,
                       const float* __restrict__ knorm, int* __restrict__ out_idx) {
    extern __shared__ __align__(128) char sm[];
    const uint32_t smb = smem_u32(sm);
    const int tid = threadIdx.x, lane = tid & 31, wid = tid >> 5;
    const int wm = wid & 1, wn = wid >> 1;
    const int mtile = blockIdx.x;

    const uint32_t mb0 = smb, mb1 = smb + 8;
    if (tid == 0) { MBARRIER_INIT(mb0, 1); MBARRIER_INIT(mb1, 1); }
    __syncthreads();

    // ldmatrix per-lane geometry
    const int la = lane & 7, lj = lane >> 3;
    const int rA = wm * 32 + (lj & 1) * 8 + la;      // A row, mf adds 16
    const int kaoff = (lj >> 1) * 16;                // byte offset in 128B row
    const uint32_t xorA = (uint32_t)(rA & 7) << 4;
    const int rB = wn * 32 + (lj >> 1) * 8 + la;     // B row, nf2 adds 16
    const int kboff = (lj & 1) * 16;
    const uint32_t xorB = (uint32_t)(rB & 7) << 4;

    float acc[2][4][4];
    #pragma unroll
    for (int a = 0; a < 2; a++)
        #pragma unroll
        for (int b = 0; b < 4; b++)
            #pragma unroll
            for (int e = 0; e < 4; e++) acc[a][b][e] = 0.f;
    float best[4]; int bidx[4];
    #pragma unroll
    for (int s = 0; s < 4; s++) { best[s] = FLT_MAX; bidx[s] = 0; }

    // prologue: fill stage 0 with g=0
    if (tid == 0) {
        MBARRIER_EXPECT_TX(mb0, STAGE_B);
        uint32_t d = smb + SM_STAGE0;
        bulk_g2s(d,             xhi_t + (size_t)(mtile * 8) * A_TILE_B, A_TILE_B, mb0);
        bulk_g2s(d + 8192,      xlo_t + (size_t)(mtile * 8) * A_TILE_B, A_TILE_B, mb0);
        bulk_g2s(d + 16384,     khi_t,                                  B_TILE_B, mb0);
        bulk_g2s(d + 32768,     klo_t,                                  B_TILE_B, mb0);
    }
    int ph0 = 0, ph1 = 0;

    for (int g = 0; g < GTOT; g++) {
        const int s = g & 1;
        __syncthreads();   // all threads done with stage s^1 before refill
        if (tid == 0 && g < GTOT - 1) {
            const int g2 = g + 1, nt2 = g2 >> 3, ch2 = g2 & 7, s2 = g2 & 1;
            const uint32_t mbx = s2 ? mb1 : mb0;
            uint32_t d = smb + SM_STAGE0 + s2 * STAGE_B;
            MBARRIER_EXPECT_TX(mbx, STAGE_B);
            bulk_g2s(d,         xhi_t + (size_t)(mtile * 8 + ch2) * A_TILE_B, A_TILE_B, mbx);
            bulk_g2s(d + 8192,  xlo_t + (size_t)(mtile * 8 + ch2) * A_TILE_B, A_TILE_B, mbx);
            bulk_g2s(d + 16384, khi_t + (size_t)(nt2 * 8 + ch2) * B_TILE_B,  B_TILE_B, mbx);
            bulk_g2s(d + 32768, klo_t + (size_t)(nt2 * 8 + ch2) * B_TILE_B,  B_TILE_B, mbx);
        }
        if (s == 0) { MBARRIER_WAIT_PARITY(mb0, ph0); ph0 ^= 1; }
        else        { MBARRIER_WAIT_PARITY(mb1, ph1); ph1 ^= 1; }

        const uint32_t sb  = smb + SM_STAGE0 + s * STAGE_B;
        const uint32_t sAh = sb, sAl = sb + 8192, sBh = sb + 16384, sBl = sb + 32768;
        #pragma unroll
        for (int ks = 0; ks < 4; ks++) {
            const int k0 = ks * 32;   // bytes (16 bf16)
            uint32_t ah[2][4], al[2][4], bh[2][4], bl[2][4];
            #pragma unroll
            for (int mf = 0; mf < 2; mf++) {
                uint32_t off = (uint32_t)(rA + mf * 16) * 128 + ((k0 + kaoff) ^ xorA);
                ldsm_x4(ah[mf], sAh + off);
                ldsm_x4(al[mf], sAl + off);
            }
            #pragma unroll
            for (int nf2 = 0; nf2 < 2; nf2++) {
                uint32_t off = (uint32_t)(rB + nf2 * 16) * 128 + ((k0 + kboff) ^ xorB);
                ldsm_x4(bh[nf2], sBh + off);
                ldsm_x4(bl[nf2], sBl + off);
            }
            #pragma unroll
            for (int mf = 0; mf < 2; mf++)
                #pragma unroll
                for (int nf = 0; nf < 4; nf++) {
                    const uint32_t* bhp = &bh[nf >> 1][(nf & 1) * 2];
                    const uint32_t* blp = &bl[nf >> 1][(nf & 1) * 2];
                    mma_bf16(acc[mf][nf], ah[mf], bhp);
                    mma_bf16(acc[mf][nf], ah[mf], blp);
                    mma_bf16(acc[mf][nf], al[mf], bhp);
                }
        }

        if ((g & 7) == 7) {   // epilogue for this n-tile
            const int n_wbase = (g >> 3) * NTILE + wn * 32;
            #pragma unroll
            for (int mf = 0; mf < 2; mf++)
                #pragma unroll
                for (int nf = 0; nf < 4; nf++) {
                    const int n0 = n_wbase + nf * 8 + (lane & 3) * 2;
                    const float kn0 = __ldg(knorm + n0);
                    const float kn1 = __ldg(knorm + n0 + 1);
                    #pragma unroll
                    for (int h = 0; h < 2; h++) {
                        const int sl = mf * 2 + h;
                        float s0 = kn0 - 2.f * acc[mf][nf][h * 2 + 0];
                        float s1 = kn1 - 2.f * acc[mf][nf][h * 2 + 1];
                        if (s0 < best[sl] || (s0 == best[sl] && n0 < bidx[sl]))
                            { best[sl] = s0; bidx[sl] = n0; }
                        if (s1 < best[sl] || (s1 == best[sl] && n0 + 1 < bidx[sl]))
                            { best[sl] = s1; bidx[sl] = n0 + 1; }
                        acc[mf][nf][h * 2 + 0] = 0.f;
                        acc[mf][nf][h * 2 + 1] = 0.f;
                    }
                }
        }
    }

    // intra-quad reduce (lanes sharing lane>>2)
    #pragma unroll
    for (int o = 1; o <= 2; o <<= 1) {
        #pragma unroll
        for (int sl = 0; sl < 4; sl++) {
            float v = __shfl_xor_sync(0xffffffffu, best[sl], o);
            int   i = __shfl_xor_sync(0xffffffffu, bidx[sl], o);
            if (v < best[sl] || (v == best[sl] && i < bidx[sl])) { best[sl] = v; bidx[sl] = i; }
        }
    }
    __syncthreads();
    float* rv = (float*)(sm + 1024);
    int*   ri = (int*)(sm + 2048);
    if ((lane & 3) == 0) {
        #pragma unroll
        for (int sl = 0; sl < 4; sl++) {
            int m = wm * 32 + (sl >> 1) * 16 + (sl & 1) * 8 + (lane >> 2);
            rv[wn * 64 + m] = best[sl];
            ri[wn * 64 + m] = bidx[sl];
        }
    }
    __syncthreads();
    if (tid < 64) {
        float bv = rv[tid]; int bi = ri[tid];
        #pragma unroll
        for (int w = 1; w < 4; w++) {
            float v = rv[w * 64 + tid]; int i = ri[w * 64 + tid];
            if (v < bv || (v == bv && i < bi)) { bv = v; bi = i; }
        }
        out_idx[mtile * MBLK + tid] = bi;
    }
    __syncthreads();
    if (tid == 0) { MBARRIER_INVAL(mb0); MBARRIER_INVAL(mb1); }
}

// ---------------- elementwise decay copy (grid-stride) ----------------
__global__ void k_scale(const float* __restrict__ src, float* __restrict__ dst, int n4) {
    for (int i = blockIdx.x * blockDim.x + threadIdx.x; i < n4;
         i += gridDim.x * blockDim.x) {
        float4 v = ((const float4*)src)[i];
        v.x *= DECAYF; v.y *= DECAYF; v.z *= DECAYF; v.w *= DECAYF;
        ((float4*)dst)[i] = v;
    }
}

// ---------------- quantized output + EMA scatter ----------------
__global__ void k_scatter(const float* __restrict__ x, const float* __restrict__ vw,
                          const int* __restrict__ idxs,
                          float* __restrict__ out_q, float* __restrict__ out_ew,
                          float* __restrict__ out_en) {
    const int t = blockIdx.x;
    const int idx = idxs[t];
    const int d4 = threadIdx.x;            // 128 threads * float4 = 512
    float4 xv = ((const float4*)(x  + (size_t)t   * D_EMBED))[d4];
    float4 vv = ((const float4*)(vw + (size_t)idx * D_EMBED))[d4];
    float4 q = make_float4(xv.x + vv.x, xv.y + vv.y, xv.z + vv.z, xv.w + vv.w);
    ((float4*)(out_q + (size_t)t * D_EMBED))[d4] = q;

    const float c = (1.0f - DECAYF) * ((float)N_CODE / (float)T_TOK);  // 0.005
    float* ew = out_ew + (size_t)idx * D_EMBED + d4 * 4;
    atomicAdd(ew + 0, c * xv.x);
    atomicAdd(ew + 1, c * xv.y);
    atomicAdd(ew + 2, c * xv.z);
    atomicAdd(ew + 3, c * xv.w);
    if (d4 == 0) atomicAdd(out_en + idx, c);
}

// ---------------- key_w_new = ema_w_new / sz (n re-reduced per block) --------
__global__ void k_finalize(const float* __restrict__ en, const float* __restrict__ ew,
                           float* __restrict__ kw) {
    __shared__ float sred[4];
    const int tid = threadIdx.x;           // 128 threads
    float v = 0.f;
    #pragma unroll
    for (int q = 0; q < N_CODE / 128; q++) v += en[q * 128 + tid];
    #pragma unroll
    for (int o = 16; o; o >>= 1) v += __shfl_xor_sync(0xffffffffu, v, o);
    if ((tid & 31) == 0) sred[tid >> 5] = v;
    __syncthreads();
    float n = sred[0] + sred[1] + sred[2] + sred[3];

    const int k = blockIdx.x;
    float sz = (en[k] + EPSF) / (n + EPSF * (float)N_CODE) * n;
    float inv = 1.0f / sz;
    float4 w = ((const float4*)(ew + (size_t)k * D_EMBED))[tid];
    w.x *= inv; w.y *= inv; w.z *= inv; w.w *= inv;
    ((float4*)(kw + (size_t)k * D_EMBED))[tid] = w;
}

// ---------------- launch ----------------
extern "C" void kernel_launch(void* const* d_in, const int* in_sizes, int n_in,
                              void* d_out, int out_size) {
    const float* x  = (const float*)d_in[0];   // [4,4096,512]
    const float* kw = (const float*)d_in[1];   // [8192,512]
    const float* vw = (const float*)d_in[2];   // [8192,512]
    const float* en = (const float*)d_in[3];   // [8192]
    const float* ew = (const float*)d_in[4];   // [8192,512]

    float* out    = (float*)d_out;
    float* out_q  = out;                                   // 16384*512 floats
    float* out_en = out_q  + (size_t)T_TOK * D_EMBED;      // 8192
    float* out_ew = out_en + N_CODE;                       // 8192*512
    float* out_kw = out_ew + (size_t)N_CODE * D_EMBED;     // 8192*512

    // scratch carved from output regions written later:
    // out_q  (32MB): xhi_t | xlo_t (tiled-swizzled bf16, dead until k_scatter)
    // out_ew (16MB): khi_t | klo_t (dead until k_scale(ew))
    // out_kw (16MB): knorm | idx   (dead until k_finalize)
    char* xhi_t = (char*)out_q;
    char* xlo_t = (char*)(out_q + (size_t)T_TOK * D_EMBED / 2);
    char* khi_t = (char*)out_ew;
    char* klo_t = (char*)(out_ew + (size_t)N_CODE * D_EMBED / 2);
    float* knorm_s = out_kw;                               // 8192 floats
    int*   idx_s   = (int*)(out_kw + N_CODE);              // 16384 ints

    cudaFuncSetAttribute(k_gemm_argmin_mma,
                         cudaFuncAttributeMaxDynamicSharedMemorySize, SM_TOTAL);

    k_split_tiled<<<(T_TOK * 64 + 255) / 256, 256>>>(x, xhi_t, xlo_t, T_TOK * 64, 6);
    k_split_tiled<<<(N_CODE * 64 + 255) / 256, 256>>>(kw, khi_t, klo_t, N_CODE * 64, 7);
    k_knorm<<<N_CODE / 8, 256>>>(kw, knorm_s);

    k_gemm_argmin_mma<<<T_TOK / MBLK, 256, SM_TOTAL>>>(xhi_t, xlo_t, khi_t, klo_t,
                                                       knorm_s, idx_s);

    k_scale<<<(N_CODE / 4 + 255) / 256, 256>>>(en, out_en, N_CODE / 4);
    k_scale<<<2048, 256>>>(ew, out_ew, N_CODE * D_EMBED / 4);
    k_scatter<<<T_TOK, 128>>>(x, vw, idx_s, out_q, out_ew, out_en);
    k_finalize<<<N_CODE, 128>>>(out_en, out_ew, out_kw);
}